// round 6
// baseline (speedup 1.0000x reference)
#include <cuda_runtime.h>
#include <math.h>

// ---------------- problem constants ----------------
#define NTOK      8192            // B*S = 4*2048
#define D_MODEL   1024
#define N_EXPERTS 8
#define N_FEAT    16
#define RAW_FEAT  512
#define PROJ_DIM  256
#define R_IN      1280            // D_MODEL + PROJ_DIM
#define R_HID     256
#define E_HID     256

// output layout (floats) : next_hidden | stage_out | gate | scaled_logits | group | rule
#define OFF_STAGE 8388608ull
#define OFF_GATE  16777216ull
#define OFF_SLOG  16842752ull
#define OFF_GRP   16908288ull
#define OFF_RULE  16941056ull

// ---------------- device scratch (no allocations allowed) ----------------
__device__ float g_hnorm[(size_t)NTOK * D_MODEL];        // 33.5 MB
__device__ float g_RI   [(size_t)NTOK * R_IN];           // 41.9 MB  (concat(h_norm, proj))
__device__ float g_P1   [(size_t)NTOK * PROJ_DIM];       //  8.4 MB
__device__ float g_RHs  [(size_t)NTOK * R_HID];          //  8.4 MB
__device__ float g_H1   [(size_t)N_EXPERTS * NTOK * E_HID]; // 67 MB
__device__ int   g_tok  [N_EXPERTS * NTOK];
__device__ float g_wt   [N_EXPERTS * NTOK];
__device__ int   g_cnt  [N_EXPERTS];

// ---------------- helpers ----------------
__device__ __forceinline__ float gelu_tanh(float x) {
    // matches jax.nn.gelu(approximate=True)
    float x3 = x * x * x;
    return 0.5f * x * (1.0f + tanhf(0.7978845608028654f * (x + 0.044715f * x3)));
}

// ================= K1: layernorm + init =================
__global__ __launch_bounds__(256) void k_layernorm(
    const float* __restrict__ hidden,
    const float* __restrict__ ln_g,
    const float* __restrict__ ln_b,
    float* __restrict__ out)
{
    int t   = blockIdx.x;
    int tid = threadIdx.x;
    const float* x = hidden + (size_t)t * D_MODEL;

    float v[4], s = 0.f, s2 = 0.f;
#pragma unroll
    for (int j = 0; j < 4; j++) {
        v[j] = x[tid + 256 * j];
        s  += v[j];
        s2 += v[j] * v[j];
    }
#pragma unroll
    for (int o = 16; o; o >>= 1) {
        s  += __shfl_down_sync(0xffffffffu, s,  o);
        s2 += __shfl_down_sync(0xffffffffu, s2, o);
    }
    __shared__ float ps[8], ps2[8];
    __shared__ float mu_s, rs_s;
    int w = tid >> 5, l = tid & 31;
    if (l == 0) { ps[w] = s; ps2[w] = s2; }
    __syncthreads();
    if (tid == 0) {
        float S = 0.f, S2 = 0.f;
#pragma unroll
        for (int i = 0; i < 8; i++) { S += ps[i]; S2 += ps2[i]; }
        float mu  = S * (1.0f / D_MODEL);
        float var = S2 * (1.0f / D_MODEL) - mu * mu;
        mu_s = mu;
        rs_s = rsqrtf(var + 1e-5f);
    }
    __syncthreads();
    float mu = mu_s, rs = rs_s;
#pragma unroll
    for (int j = 0; j < 4; j++) {
        int d = tid + 256 * j;
        float hn = (v[j] - mu) * rs * ln_g[d] + ln_b[d];
        g_hnorm[(size_t)t * D_MODEL + d] = hn;
        g_RI[(size_t)t * R_IN + d]       = hn;
        out[OFF_STAGE + (size_t)t * D_MODEL + d] = 0.0f;   // zero stage_out
    }
    if (t == 0 && tid < N_EXPERTS) g_cnt[tid] = 0;         // reset dispatch counters
}

// ================= generic SGEMM: C = act(A @ B + bias) =================
// BM=BN=64, BK=16, 256 threads, 4x4 microtile. M,N are multiples of 64 (no guards).
template <int ACT>
__global__ __launch_bounds__(256) void sgemm_bias(
    const float* __restrict__ A, int lda,
    const float* __restrict__ B, int ldb,
    const float* __restrict__ bias,
    float* __restrict__ C, int ldc,
    int K)
{
    __shared__ __align__(16) float As[16][68];
    __shared__ __align__(16) float Bs[16][64];
    const int t  = threadIdx.x;
    const int m0 = blockIdx.x * 64, n0 = blockIdx.y * 64;
    const int ty = t >> 4, tx = t & 15;
    const int acol = t & 15, arow = t >> 4;   // A: rows arow+16i, col k0+acol
    const int bcol = t & 63, brow = t >> 6;   // B: rows k0+brow+4i, col n0+bcol

    float acc[4][4] = {};
    const float* Ap = A + (size_t)m0 * lda;
    const float* Bp = B + n0;

    for (int k0 = 0; k0 < K; k0 += 16) {
#pragma unroll
        for (int i = 0; i < 4; i++)
            As[acol][arow + 16 * i] = Ap[(size_t)(arow + 16 * i) * lda + k0 + acol];
#pragma unroll
        for (int i = 0; i < 4; i++)
            Bs[brow + 4 * i][bcol] = Bp[(size_t)(k0 + brow + 4 * i) * ldb + bcol];
        __syncthreads();
#pragma unroll
        for (int k = 0; k < 16; k++) {
            float4 a4 = *reinterpret_cast<const float4*>(&As[k][ty * 4]);
            float4 b4 = *reinterpret_cast<const float4*>(&Bs[k][tx * 4]);
            float av[4] = {a4.x, a4.y, a4.z, a4.w};
            float bv[4] = {b4.x, b4.y, b4.z, b4.w};
#pragma unroll
            for (int i = 0; i < 4; i++)
#pragma unroll
                for (int j = 0; j < 4; j++)
                    acc[i][j] = fmaf(av[i], bv[j], acc[i][j]);
        }
        __syncthreads();
    }
    float bb[4];
#pragma unroll
    for (int j = 0; j < 4; j++) bb[j] = bias[n0 + tx * 4 + j];
#pragma unroll
    for (int i = 0; i < 4; i++) {
        float4 vv;
        float* pv = &vv.x;
#pragma unroll
        for (int j = 0; j < 4; j++) {
            float v = acc[i][j] + bb[j];
            if (ACT == 1) v = gelu_tanh(v);
            pv[j] = v;
        }
        *reinterpret_cast<float4*>(&C[(size_t)(m0 + ty * 4 + i) * ldc + n0 + tx * 4]) = vv;
    }
}

// ================= K5: router logits, top-2 softmax, small outputs, dispatch =================
__global__ __launch_bounds__(256) void k_router(
    const float* __restrict__ r_w2, const float* __restrict__ r_b2,
    const float* __restrict__ feat,
    const float* __restrict__ rr_w, const float* __restrict__ rr_b,
    float* __restrict__ out)
{
    int w = threadIdx.x >> 5, l = threadIdx.x & 31;
    int t = blockIdx.x * 8 + w;
    const float* rh = g_RHs + (size_t)t * R_HID;

    float acc[8] = {};
    for (int k = l; k < R_HID; k += 32) {
        float v = rh[k];
#pragma unroll
        for (int e = 0; e < 8; e++) acc[e] = fmaf(v, r_w2[k * 8 + e], acc[e]);
    }
#pragma unroll
    for (int o = 16; o; o >>= 1)
#pragma unroll
        for (int e = 0; e < 8; e++) acc[e] += __shfl_down_sync(0xffffffffu, acc[e], o);

    if (l == 0) {
        float lg[8];
#pragma unroll
        for (int e = 0; e < 8; e++) lg[e] = acc[e] + r_b2[e];
        // top-2 threshold (matches lax.top_k: second element of sorted desc)
        int i1 = 0; float m1 = lg[0];
#pragma unroll
        for (int e = 1; e < 8; e++) if (lg[e] > m1) { m1 = lg[e]; i1 = e; }
        float m2 = -3.4e38f;
#pragma unroll
        for (int e = 0; e < 8; e++) if (e != i1 && lg[e] > m2) m2 = lg[e];
        float Z = 0.f, g[8];
#pragma unroll
        for (int e = 0; e < 8; e++) {
            if (lg[e] >= m2) { g[e] = expf(lg[e] - m1); Z += g[e]; }
            else g[e] = 0.f;
        }
        float invZ = 1.0f / Z;
#pragma unroll
        for (int e = 0; e < 8; e++) {
            g[e] *= invZ;
            out[OFF_GATE + (size_t)t * 8 + e] = g[e];
            out[OFF_SLOG + (size_t)t * 8 + e] = lg[e];   // TEMP = 1
        }
#pragma unroll
        for (int gi = 0; gi < 4; gi++)
            out[OFF_GRP + (size_t)t * 4 + gi] = g[2 * gi] + g[2 * gi + 1];
        // rule logits
        float fv[16];
#pragma unroll
        for (int i = 0; i < 16; i++) fv[i] = feat[(size_t)t * 16 + i];
#pragma unroll
        for (int e = 0; e < 8; e++) {
            float r = rr_b[e];
#pragma unroll
            for (int i = 0; i < 16; i++) r = fmaf(fv[i], rr_w[i * 8 + e], r);
            out[OFF_RULE + (size_t)t * 8 + e] = r;
        }
        // dispatch to per-expert lists
#pragma unroll
        for (int e = 0; e < 8; e++) {
            if (g[e] > 0.f) {
                int p = atomicAdd(&g_cnt[e], 1);
                g_tok[e * NTOK + p] = t;
                g_wt [e * NTOK + p] = g[e];
            }
        }
    }
}

// ================= K6: expert GEMM1 (gathered): H1 = gelu(hnorm[toks] @ W1 + b1) =================
__global__ __launch_bounds__(256) void k_expert1(
    const float* __restrict__ e_w1, const float* __restrict__ e_b1)
{
    int e = blockIdx.z;
    int M = g_cnt[e];
    int m0 = blockIdx.x * 64;
    if (m0 >= M) return;
    int n0 = blockIdx.y * 64;

    __shared__ __align__(16) float As[16][68];
    __shared__ __align__(16) float Bs[16][64];
    __shared__ int rtok[64];

    const int t = threadIdx.x;
    if (t < 64) rtok[t] = g_tok[e * NTOK + min(m0 + t, M - 1)];

    const int ty = t >> 4, tx = t & 15;
    const int acol = t & 15, arow = t >> 4;
    const int bcol = t & 63, brow = t >> 6;
    const float* Bp = e_w1 + (size_t)e * D_MODEL * E_HID + n0;

    float acc[4][4] = {};
    __syncthreads();
    for (int k0 = 0; k0 < D_MODEL; k0 += 16) {
#pragma unroll
        for (int i = 0; i < 4; i++) {
            int r = arow + 16 * i;
            As[acol][r] = g_hnorm[(size_t)rtok[r] * D_MODEL + k0 + acol];
        }
#pragma unroll
        for (int i = 0; i < 4; i++)
            Bs[brow + 4 * i][bcol] = Bp[(size_t)(k0 + brow + 4 * i) * E_HID + bcol];
        __syncthreads();
#pragma unroll
        for (int k = 0; k < 16; k++) {
            float4 a4 = *reinterpret_cast<const float4*>(&As[k][ty * 4]);
            float4 b4 = *reinterpret_cast<const float4*>(&Bs[k][tx * 4]);
            float av[4] = {a4.x, a4.y, a4.z, a4.w};
            float bv[4] = {b4.x, b4.y, b4.z, b4.w};
#pragma unroll
            for (int i = 0; i < 4; i++)
#pragma unroll
                for (int j = 0; j < 4; j++)
                    acc[i][j] = fmaf(av[i], bv[j], acc[i][j]);
        }
        __syncthreads();
    }
    float bb[4];
#pragma unroll
    for (int j = 0; j < 4; j++) bb[j] = e_b1[e * E_HID + n0 + tx * 4 + j];
#pragma unroll
    for (int i = 0; i < 4; i++) {
        int m = m0 + ty * 4 + i;
        if (m < M) {
            float4 vv;
            float* pv = &vv.x;
#pragma unroll
            for (int j = 0; j < 4; j++) pv[j] = gelu_tanh(acc[i][j] + bb[j]);
            *reinterpret_cast<float4*>(
                &g_H1[((size_t)e * NTOK + m) * E_HID + n0 + tx * 4]) = vv;
        }
    }
}

// ================= K7: expert GEMM2: stage_out += w * (H1 @ W2 + b2) =================
__global__ __launch_bounds__(256) void k_expert2(
    const float* __restrict__ e_w2, const float* __restrict__ e_b2,
    float* __restrict__ out)
{
    int e = blockIdx.z;
    int M = g_cnt[e];
    int m0 = blockIdx.x * 64;
    if (m0 >= M) return;
    int n0 = blockIdx.y * 64;

    __shared__ __align__(16) float As[16][68];
    __shared__ __align__(16) float Bs[16][64];

    const int t = threadIdx.x;
    const int ty = t >> 4, tx = t & 15;
    const int acol = t & 15, arow = t >> 4;
    const int bcol = t & 63, brow = t >> 6;
    const float* Ap = g_H1 + (size_t)e * NTOK * E_HID;
    const float* Bp = e_w2 + (size_t)e * E_HID * D_MODEL + n0;

    float acc[4][4] = {};
    for (int k0 = 0; k0 < E_HID; k0 += 16) {
#pragma unroll
        for (int i = 0; i < 4; i++) {
            int m = min(m0 + arow + 16 * i, M - 1);
            As[acol][arow + 16 * i] = Ap[(size_t)m * E_HID + k0 + acol];
        }
#pragma unroll
        for (int i = 0; i < 4; i++)
            Bs[brow + 4 * i][bcol] = Bp[(size_t)(k0 + brow + 4 * i) * D_MODEL + bcol];
        __syncthreads();
#pragma unroll
        for (int k = 0; k < 16; k++) {
            float4 a4 = *reinterpret_cast<const float4*>(&As[k][ty * 4]);
            float4 b4 = *reinterpret_cast<const float4*>(&Bs[k][tx * 4]);
            float av[4] = {a4.x, a4.y, a4.z, a4.w};
            float bv[4] = {b4.x, b4.y, b4.z, b4.w};
#pragma unroll
            for (int i = 0; i < 4; i++)
#pragma unroll
                for (int j = 0; j < 4; j++)
                    acc[i][j] = fmaf(av[i], bv[j], acc[i][j]);
        }
        __syncthreads();
    }
    float bb[4];
#pragma unroll
    for (int j = 0; j < 4; j++) bb[j] = e_b2[e * D_MODEL + n0 + tx * 4 + j];
#pragma unroll
    for (int i = 0; i < 4; i++) {
        int m = m0 + ty * 4 + i;
        if (m < M) {
            int   tok = g_tok[e * NTOK + m];
            float wgt = g_wt [e * NTOK + m];
            float* dst = out + OFF_STAGE + (size_t)tok * D_MODEL + n0 + tx * 4;
#pragma unroll
            for (int j = 0; j < 4; j++)
                atomicAdd(&dst[j], (acc[i][j] + bb[j]) * wgt);
        }
    }
}

// ================= K8: next_hidden = hidden + alpha * stage_out =================
__global__ __launch_bounds__(256) void k_finalize(
    const float* __restrict__ hidden,
    const float* __restrict__ alpha,
    float* __restrict__ out)
{
    size_t i = ((size_t)blockIdx.x * 256 + threadIdx.x) * 4;
    float a = alpha[0];
    float4 h = *reinterpret_cast<const float4*>(hidden + i);
    float4 s = *reinterpret_cast<const float4*>(out + OFF_STAGE + i);
    float4 r;
    r.x = h.x + a * s.x;
    r.y = h.y + a * s.y;
    r.z = h.z + a * s.z;
    r.w = h.w + a * s.w;
    *reinterpret_cast<float4*>(out + i) = r;
}

// ================= host launcher =================
extern "C" void kernel_launch(void* const* d_in, const int* in_sizes, int n_in,
                              void* d_out, int out_size)
{
    const float* hidden = (const float*)d_in[0];
    const float* feat   = (const float*)d_in[1];
    const float* bank   = (const float*)d_in[2];   // (NTOK, 512) flat
    // d_in[3] = item_seq_len (unused by reference outputs)
    const float* ln_g   = (const float*)d_in[4];
    const float* ln_b   = (const float*)d_in[5];
    const float* fp_w1  = (const float*)d_in[6];
    const float* fp_b1  = (const float*)d_in[7];
    const float* fp_w2  = (const float*)d_in[8];
    const float* fp_b2  = (const float*)d_in[9];
    const float* r_w1   = (const float*)d_in[10];
    const float* r_b1   = (const float*)d_in[11];
    const float* r_w2   = (const float*)d_in[12];
    const float* r_b2   = (const float*)d_in[13];
    const float* rr_w   = (const float*)d_in[14];
    const float* rr_b   = (const float*)d_in[15];
    const float* e_w1   = (const float*)d_in[16];
    const float* e_b1   = (const float*)d_in[17];
    const float* e_w2   = (const float*)d_in[18];
    const float* e_b2   = (const float*)d_in[19];
    const float* alpha  = (const float*)d_in[20];
    float* out = (float*)d_out;

    float *p_RI, *p_P1, *p_RHs;
    cudaGetSymbolAddress((void**)&p_RI,  g_RI);
    cudaGetSymbolAddress((void**)&p_P1,  g_P1);
    cudaGetSymbolAddress((void**)&p_RHs, g_RHs);

    // K1: layernorm -> g_hnorm / g_RI[:, :1024], zero stage_out, reset counters
    k_layernorm<<<NTOK, 256>>>(hidden, ln_g, ln_b, out);

    // K2: P1 = gelu(bank @ fp_w1 + fp_b1)        [8192x512 @ 512x256]
    sgemm_bias<1><<<dim3(NTOK / 64, PROJ_DIM / 64), 256>>>(
        bank, RAW_FEAT, fp_w1, PROJ_DIM, fp_b1, p_P1, PROJ_DIM, RAW_FEAT);

    // K3: proj = P1 @ fp_w2 + fp_b2  -> g_RI[:, 1024:1280]
    sgemm_bias<0><<<dim3(NTOK / 64, PROJ_DIM / 64), 256>>>(
        p_P1, PROJ_DIM, fp_w2, PROJ_DIM, fp_b2, p_RI + D_MODEL, R_IN, PROJ_DIM);

    // K4: RH = gelu(RI @ r_w1 + r_b1)            [8192x1280 @ 1280x256]
    sgemm_bias<1><<<dim3(NTOK / 64, R_HID / 64), 256>>>(
        p_RI, R_IN, r_w1, R_HID, r_b1, p_RHs, R_HID, R_IN);

    // K5: logits, top-2 softmax, small outputs, expert dispatch
    k_router<<<NTOK / 8, 256>>>(r_w2, r_b2, feat, rr_w, rr_b, out);

    // K6: per-expert gathered GEMM1 (gelu)
    k_expert1<<<dim3(NTOK / 64, E_HID / 64, N_EXPERTS), 256>>>(e_w1, e_b1);

    // K7: per-expert GEMM2, gate-weighted atomic accumulate into stage_out
    k_expert2<<<dim3(NTOK / 64, D_MODEL / 64, N_EXPERTS), 256>>>(e_w2, e_b2, out);

    // K8: next_hidden = hidden + alpha * stage_out
    k_finalize<<<(NTOK * D_MODEL) / (256 * 4), 256>>>(hidden, alpha, out);
}

// round 7
// speedup vs baseline: 1.0505x; 1.0505x over previous
#include <cuda_runtime.h>
#include <math.h>

// ---------------- problem constants ----------------
#define NTOK      8192            // B*S = 4*2048
#define D_MODEL   1024
#define N_EXPERTS 8
#define N_FEAT    16
#define RAW_FEAT  512
#define PROJ_DIM  256
#define R_IN      1280            // D_MODEL + PROJ_DIM
#define R_HID     256
#define E_HID     256

// output layout (floats) : next_hidden | stage_out | gate | scaled_logits | group | rule
#define OFF_STAGE 8388608ull
#define OFF_GATE  16777216ull
#define OFF_SLOG  16842752ull
#define OFF_GRP   16908288ull
#define OFF_RULE  16941056ull

// ---------------- device scratch (no allocations allowed) ----------------
__device__ float g_hnorm[(size_t)NTOK * D_MODEL];        // 33.5 MB
__device__ float g_RI   [(size_t)NTOK * R_IN];           // 41.9 MB  (concat(h_norm, proj))
__device__ float g_P1   [(size_t)NTOK * PROJ_DIM];       //  8.4 MB
__device__ float g_RHs  [(size_t)NTOK * R_HID];          //  8.4 MB
__device__ float g_H1   [(size_t)N_EXPERTS * NTOK * E_HID]; // 67 MB
__device__ int   g_tok  [N_EXPERTS * NTOK];
__device__ float g_wt   [N_EXPERTS * NTOK];
__device__ int   g_cnt  [N_EXPERTS];

// ---------------- helpers ----------------
__device__ __forceinline__ float gelu_tanh(float x) {
    // matches jax.nn.gelu(approximate=True)
    float x3 = x * x * x;
    return 0.5f * x * (1.0f + tanhf(0.7978845608028654f * (x + 0.044715f * x3)));
}

// ================= K1: layernorm + init =================
__global__ __launch_bounds__(256) void k_layernorm(
    const float* __restrict__ hidden,
    const float* __restrict__ ln_g,
    const float* __restrict__ ln_b,
    float* __restrict__ out)
{
    int t   = blockIdx.x;
    int tid = threadIdx.x;
    const float* x = hidden + (size_t)t * D_MODEL;

    float v[4], s = 0.f, s2 = 0.f;
#pragma unroll
    for (int j = 0; j < 4; j++) {
        v[j] = x[tid + 256 * j];
        s  += v[j];
        s2 += v[j] * v[j];
    }
#pragma unroll
    for (int o = 16; o; o >>= 1) {
        s  += __shfl_down_sync(0xffffffffu, s,  o);
        s2 += __shfl_down_sync(0xffffffffu, s2, o);
    }
    __shared__ float ps[8], ps2[8];
    __shared__ float mu_s, rs_s;
    int w = tid >> 5, l = tid & 31;
    if (l == 0) { ps[w] = s; ps2[w] = s2; }
    __syncthreads();
    if (tid == 0) {
        float S = 0.f, S2 = 0.f;
#pragma unroll
        for (int i = 0; i < 8; i++) { S += ps[i]; S2 += ps2[i]; }
        float mu  = S * (1.0f / D_MODEL);
        float var = S2 * (1.0f / D_MODEL) - mu * mu;
        mu_s = mu;
        rs_s = rsqrtf(var + 1e-5f);
    }
    __syncthreads();
    float mu = mu_s, rs = rs_s;
#pragma unroll
    for (int j = 0; j < 4; j++) {
        int d = tid + 256 * j;
        float hn = (v[j] - mu) * rs * ln_g[d] + ln_b[d];
        g_hnorm[(size_t)t * D_MODEL + d] = hn;
        g_RI[(size_t)t * R_IN + d]       = hn;
        out[OFF_STAGE + (size_t)t * D_MODEL + d] = 0.0f;   // zero stage_out
    }
    if (t == 0 && tid < N_EXPERTS) g_cnt[tid] = 0;         // reset dispatch counters
}

// ================= generic SGEMM: C = act(A @ B + bias) =================
// BM=BN=64, BK=16, 256 threads, 4x4 microtile. M,N are multiples of 64 (no guards).
template <int ACT>
__global__ __launch_bounds__(256) void sgemm_bias(
    const float* __restrict__ A, int lda,
    const float* __restrict__ B, int ldb,
    const float* __restrict__ bias,
    float* __restrict__ C, int ldc,
    int K)
{
    __shared__ __align__(16) float As[16][68];
    __shared__ __align__(16) float Bs[16][64];
    const int t  = threadIdx.x;
    const int m0 = blockIdx.x * 64, n0 = blockIdx.y * 64;
    const int ty = t >> 4, tx = t & 15;
    const int acol = t & 15, arow = t >> 4;   // A: rows arow+16i, col k0+acol
    const int bcol = t & 63, brow = t >> 6;   // B: rows k0+brow+4i, col n0+bcol

    float acc[4][4] = {};
    const float* Ap = A + (size_t)m0 * lda;
    const float* Bp = B + n0;

    for (int k0 = 0; k0 < K; k0 += 16) {
#pragma unroll
        for (int i = 0; i < 4; i++)
            As[acol][arow + 16 * i] = Ap[(size_t)(arow + 16 * i) * lda + k0 + acol];
#pragma unroll
        for (int i = 0; i < 4; i++)
            Bs[brow + 4 * i][bcol] = Bp[(size_t)(k0 + brow + 4 * i) * ldb + bcol];
        __syncthreads();
#pragma unroll
        for (int k = 0; k < 16; k++) {
            float4 a4 = *reinterpret_cast<const float4*>(&As[k][ty * 4]);
            float4 b4 = *reinterpret_cast<const float4*>(&Bs[k][tx * 4]);
            float av[4] = {a4.x, a4.y, a4.z, a4.w};
            float bv[4] = {b4.x, b4.y, b4.z, b4.w};
#pragma unroll
            for (int i = 0; i < 4; i++)
#pragma unroll
                for (int j = 0; j < 4; j++)
                    acc[i][j] = fmaf(av[i], bv[j], acc[i][j]);
        }
        __syncthreads();
    }
    float bb[4];
#pragma unroll
    for (int j = 0; j < 4; j++) bb[j] = bias[n0 + tx * 4 + j];
#pragma unroll
    for (int i = 0; i < 4; i++) {
        float4 vv;
        float* pv = &vv.x;
#pragma unroll
        for (int j = 0; j < 4; j++) {
            float v = acc[i][j] + bb[j];
            if (ACT == 1) v = gelu_tanh(v);
            pv[j] = v;
        }
        *reinterpret_cast<float4*>(&C[(size_t)(m0 + ty * 4 + i) * ldc + n0 + tx * 4]) = vv;
    }
}

// ================= K5: router logits, top-2 softmax, small outputs, dispatch =================
__global__ __launch_bounds__(256) void k_router(
    const float* __restrict__ r_w2, const float* __restrict__ r_b2,
    const float* __restrict__ feat,
    const float* __restrict__ rr_w, const float* __restrict__ rr_b,
    float* __restrict__ out)
{
    int w = threadIdx.x >> 5, l = threadIdx.x & 31;
    int t = blockIdx.x * 8 + w;
    const float* rh = g_RHs + (size_t)t * R_HID;

    float acc[8] = {};
    for (int k = l; k < R_HID; k += 32) {
        float v = rh[k];
#pragma unroll
        for (int e = 0; e < 8; e++) acc[e] = fmaf(v, r_w2[k * 8 + e], acc[e]);
    }
#pragma unroll
    for (int o = 16; o; o >>= 1)
#pragma unroll
        for (int e = 0; e < 8; e++) acc[e] += __shfl_down_sync(0xffffffffu, acc[e], o);

    if (l == 0) {
        float lg[8];
#pragma unroll
        for (int e = 0; e < 8; e++) lg[e] = acc[e] + r_b2[e];
        // top-2 threshold (matches lax.top_k: second element of sorted desc)
        int i1 = 0; float m1 = lg[0];
#pragma unroll
        for (int e = 1; e < 8; e++) if (lg[e] > m1) { m1 = lg[e]; i1 = e; }
        float m2 = -3.4e38f;
#pragma unroll
        for (int e = 0; e < 8; e++) if (e != i1 && lg[e] > m2) m2 = lg[e];
        float Z = 0.f, g[8];
#pragma unroll
        for (int e = 0; e < 8; e++) {
            if (lg[e] >= m2) { g[e] = expf(lg[e] - m1); Z += g[e]; }
            else g[e] = 0.f;
        }
        float invZ = 1.0f / Z;
#pragma unroll
        for (int e = 0; e < 8; e++) {
            g[e] *= invZ;
            out[OFF_GATE + (size_t)t * 8 + e] = g[e];
            out[OFF_SLOG + (size_t)t * 8 + e] = lg[e];   // TEMP = 1
        }
#pragma unroll
        for (int gi = 0; gi < 4; gi++)
            out[OFF_GRP + (size_t)t * 4 + gi] = g[2 * gi] + g[2 * gi + 1];
        // rule logits
        float fv[16];
#pragma unroll
        for (int i = 0; i < 16; i++) fv[i] = feat[(size_t)t * 16 + i];
#pragma unroll
        for (int e = 0; e < 8; e++) {
            float r = rr_b[e];
#pragma unroll
            for (int i = 0; i < 16; i++) r = fmaf(fv[i], rr_w[i * 8 + e], r);
            out[OFF_RULE + (size_t)t * 8 + e] = r;
        }
        // dispatch to per-expert lists
#pragma unroll
        for (int e = 0; e < 8; e++) {
            if (g[e] > 0.f) {
                int p = atomicAdd(&g_cnt[e], 1);
                g_tok[e * NTOK + p] = t;
                g_wt [e * NTOK + p] = g[e];
            }
        }
    }
}

// ================= K6: expert GEMM1 (gathered): H1 = gelu(hnorm[toks] @ W1 + b1) =================
__global__ __launch_bounds__(256) void k_expert1(
    const float* __restrict__ e_w1, const float* __restrict__ e_b1)
{
    int e = blockIdx.z;
    int M = g_cnt[e];
    int m0 = blockIdx.x * 64;
    if (m0 >= M) return;
    int n0 = blockIdx.y * 64;

    __shared__ __align__(16) float As[16][68];
    __shared__ __align__(16) float Bs[16][64];
    __shared__ int rtok[64];

    const int t = threadIdx.x;
    if (t < 64) rtok[t] = g_tok[e * NTOK + min(m0 + t, M - 1)];

    const int ty = t >> 4, tx = t & 15;
    const int acol = t & 15, arow = t >> 4;
    const int bcol = t & 63, brow = t >> 6;
    const float* Bp = e_w1 + (size_t)e * D_MODEL * E_HID + n0;

    float acc[4][4] = {};
    __syncthreads();
    for (int k0 = 0; k0 < D_MODEL; k0 += 16) {
#pragma unroll
        for (int i = 0; i < 4; i++) {
            int r = arow + 16 * i;
            As[acol][r] = g_hnorm[(size_t)rtok[r] * D_MODEL + k0 + acol];
        }
#pragma unroll
        for (int i = 0; i < 4; i++)
            Bs[brow + 4 * i][bcol] = Bp[(size_t)(k0 + brow + 4 * i) * E_HID + bcol];
        __syncthreads();
#pragma unroll
        for (int k = 0; k < 16; k++) {
            float4 a4 = *reinterpret_cast<const float4*>(&As[k][ty * 4]);
            float4 b4 = *reinterpret_cast<const float4*>(&Bs[k][tx * 4]);
            float av[4] = {a4.x, a4.y, a4.z, a4.w};
            float bv[4] = {b4.x, b4.y, b4.z, b4.w};
#pragma unroll
            for (int i = 0; i < 4; i++)
#pragma unroll
                for (int j = 0; j < 4; j++)
                    acc[i][j] = fmaf(av[i], bv[j], acc[i][j]);
        }
        __syncthreads();
    }
    float bb[4];
#pragma unroll
    for (int j = 0; j < 4; j++) bb[j] = e_b1[e * E_HID + n0 + tx * 4 + j];
#pragma unroll
    for (int i = 0; i < 4; i++) {
        int m = m0 + ty * 4 + i;
        if (m < M) {
            float4 vv;
            float* pv = &vv.x;
#pragma unroll
            for (int j = 0; j < 4; j++) pv[j] = gelu_tanh(acc[i][j] + bb[j]);
            *reinterpret_cast<float4*>(
                &g_H1[((size_t)e * NTOK + m) * E_HID + n0 + tx * 4]) = vv;
        }
    }
}

// ================= K7: expert GEMM2: stage_out += w * (H1 @ W2 + b2) =================
__global__ __launch_bounds__(256) void k_expert2(
    const float* __restrict__ e_w2, const float* __restrict__ e_b2,
    float* __restrict__ out)
{
    int e = blockIdx.z;
    int M = g_cnt[e];
    int m0 = blockIdx.x * 64;
    if (m0 >= M) return;
    int n0 = blockIdx.y * 64;

    __shared__ __align__(16) float As[16][68];
    __shared__ __align__(16) float Bs[16][64];

    const int t = threadIdx.x;
    const int ty = t >> 4, tx = t & 15;
    const int acol = t & 15, arow = t >> 4;
    const int bcol = t & 63, brow = t >> 6;
    const float* Ap = g_H1 + (size_t)e * NTOK * E_HID;
    const float* Bp = e_w2 + (size_t)e * E_HID * D_MODEL + n0;

    float acc[4][4] = {};
    for (int k0 = 0; k0 < E_HID; k0 += 16) {
#pragma unroll
        for (int i = 0; i < 4; i++) {
            int m = min(m0 + arow + 16 * i, M - 1);
            As[acol][arow + 16 * i] = Ap[(size_t)m * E_HID + k0 + acol];
        }
#pragma unroll
        for (int i = 0; i < 4; i++)
            Bs[brow + 4 * i][bcol] = Bp[(size_t)(k0 + brow + 4 * i) * D_MODEL + bcol];
        __syncthreads();
#pragma unroll
        for (int k = 0; k < 16; k++) {
            float4 a4 = *reinterpret_cast<const float4*>(&As[k][ty * 4]);
            float4 b4 = *reinterpret_cast<const float4*>(&Bs[k][tx * 4]);
            float av[4] = {a4.x, a4.y, a4.z, a4.w};
            float bv[4] = {b4.x, b4.y, b4.z, b4.w};
#pragma unroll
            for (int i = 0; i < 4; i++)
#pragma unroll
                for (int j = 0; j < 4; j++)
                    acc[i][j] = fmaf(av[i], bv[j], acc[i][j]);
        }
        __syncthreads();
    }
    float bb[4];
#pragma unroll
    for (int j = 0; j < 4; j++) bb[j] = e_b2[e * D_MODEL + n0 + tx * 4 + j];
#pragma unroll
    for (int i = 0; i < 4; i++) {
        int m = m0 + ty * 4 + i;
        if (m < M) {
            int   tok = g_tok[e * NTOK + m];
            float wgt = g_wt [e * NTOK + m];
            float* dst = out + OFF_STAGE + (size_t)tok * D_MODEL + n0 + tx * 4;
#pragma unroll
            for (int j = 0; j < 4; j++)
                atomicAdd(&dst[j], (acc[i][j] + bb[j]) * wgt);
        }
    }
}

// ================= K8: next_hidden = hidden + alpha * stage_out =================
__global__ __launch_bounds__(256) void k_finalize(
    const float* __restrict__ hidden,
    const float* __restrict__ alpha,
    float* __restrict__ out)
{
    size_t i = ((size_t)blockIdx.x * 256 + threadIdx.x) * 4;
    float a = alpha[0];
    float4 h = *reinterpret_cast<const float4*>(hidden + i);
    float4 s = *reinterpret_cast<const float4*>(out + OFF_STAGE + i);
    float4 r;
    r.x = h.x + a * s.x;
    r.y = h.y + a * s.y;
    r.z = h.z + a * s.z;
    r.w = h.w + a * s.w;
    *reinterpret_cast<float4*>(out + i) = r;
}

// ================= host launcher =================
extern "C" void kernel_launch(void* const* d_in, const int* in_sizes, int n_in,
                              void* d_out, int out_size)
{
    const float* hidden = (const float*)d_in[0];
    const float* feat   = (const float*)d_in[1];
    const float* bank   = (const float*)d_in[2];   // (NTOK, 512) flat
    // d_in[3] = item_seq_len (unused by reference outputs)
    const float* ln_g   = (const float*)d_in[4];
    const float* ln_b   = (const float*)d_in[5];
    const float* fp_w1  = (const float*)d_in[6];
    const float* fp_b1  = (const float*)d_in[7];
    const float* fp_w2  = (const float*)d_in[8];
    const float* fp_b2  = (const float*)d_in[9];
    const float* r_w1   = (const float*)d_in[10];
    const float* r_b1   = (const float*)d_in[11];
    const float* r_w2   = (const float*)d_in[12];
    const float* r_b2   = (const float*)d_in[13];
    const float* rr_w   = (const float*)d_in[14];
    const float* rr_b   = (const float*)d_in[15];
    const float* e_w1   = (const float*)d_in[16];
    const float* e_b1   = (const float*)d_in[17];
    const float* e_w2   = (const float*)d_in[18];
    const float* e_b2   = (const float*)d_in[19];
    const float* alpha  = (const float*)d_in[20];
    float* out = (float*)d_out;

    float *p_RI, *p_P1, *p_RHs;
    cudaGetSymbolAddress((void**)&p_RI,  g_RI);
    cudaGetSymbolAddress((void**)&p_P1,  g_P1);
    cudaGetSymbolAddress((void**)&p_RHs, g_RHs);

    // K1: layernorm -> g_hnorm / g_RI[:, :1024], zero stage_out, reset counters
    k_layernorm<<<NTOK, 256>>>(hidden, ln_g, ln_b, out);

    // K2: P1 = gelu(bank @ fp_w1 + fp_b1)        [8192x512 @ 512x256]
    sgemm_bias<1><<<dim3(NTOK / 64, PROJ_DIM / 64), 256>>>(
        bank, RAW_FEAT, fp_w1, PROJ_DIM, fp_b1, p_P1, PROJ_DIM, RAW_FEAT);

    // K3: proj = P1 @ fp_w2 + fp_b2  -> g_RI[:, 1024:1280]
    sgemm_bias<0><<<dim3(NTOK / 64, PROJ_DIM / 64), 256>>>(
        p_P1, PROJ_DIM, fp_w2, PROJ_DIM, fp_b2, p_RI + D_MODEL, R_IN, PROJ_DIM);

    // K4: RH = gelu(RI @ r_w1 + r_b1)            [8192x1280 @ 1280x256]
    sgemm_bias<1><<<dim3(NTOK / 64, R_HID / 64), 256>>>(
        p_RI, R_IN, r_w1, R_HID, r_b1, p_RHs, R_HID, R_IN);

    // K5: logits, top-2 softmax, small outputs, expert dispatch
    k_router<<<NTOK / 8, 256>>>(r_w2, r_b2, feat, rr_w, rr_b, out);

    // K6: per-expert gathered GEMM1 (gelu)
    k_expert1<<<dim3(NTOK / 64, E_HID / 64, N_EXPERTS), 256>>>(e_w1, e_b1);

    // K7: per-expert GEMM2, gate-weighted atomic accumulate into stage_out
    k_expert2<<<dim3(NTOK / 64, D_MODEL / 64, N_EXPERTS), 256>>>(e_w2, e_b2, out);

    // K8: next_hidden = hidden + alpha * stage_out
    k_finalize<<<(NTOK * D_MODEL) / (256 * 4), 256>>>(hidden, alpha, out);
}

// round 8
// speedup vs baseline: 1.4311x; 1.3624x over previous
#include <cuda_runtime.h>
#include <math.h>

// ---------------- problem constants ----------------
#define NTOK      8192            // B*S = 4*2048
#define D_MODEL   1024
#define N_EXPERTS 8
#define N_FEAT    16
#define RAW_FEAT  512
#define PROJ_DIM  256
#define R_IN      1280            // D_MODEL + PROJ_DIM
#define R_HID     256
#define E_HID     256

// output layout (floats) : next_hidden | stage_out | gate | scaled_logits | group | rule
#define OFF_STAGE 8388608ull
#define OFF_GATE  16777216ull
#define OFF_SLOG  16842752ull
#define OFF_GRP   16908288ull
#define OFF_RULE  16941056ull

// ---------------- device scratch (no allocations allowed) ----------------
__device__ float g_hnorm[(size_t)NTOK * D_MODEL];
__device__ float g_RI   [(size_t)NTOK * R_IN];
__device__ float g_P1   [(size_t)NTOK * PROJ_DIM];
__device__ float g_RHs  [(size_t)NTOK * R_HID];
__device__ float g_H1   [(size_t)N_EXPERTS * NTOK * E_HID];
__device__ int   g_tok  [N_EXPERTS * NTOK];
__device__ float g_wt   [N_EXPERTS * NTOK];
__device__ int   g_cnt  [N_EXPERTS];

// ---------------- helpers ----------------
__device__ __forceinline__ float gelu_tanh(float x) {
    float x3 = x * x * x;
    return 0.5f * x * (1.0f + tanhf(0.7978845608028654f * (x + 0.044715f * x3)));
}

// ================= K1: layernorm + init =================
__global__ __launch_bounds__(256) void k_layernorm(
    const float* __restrict__ hidden,
    const float* __restrict__ ln_g,
    const float* __restrict__ ln_b,
    float* __restrict__ out)
{
    int t   = blockIdx.x;
    int tid = threadIdx.x;
    const float* x = hidden + (size_t)t * D_MODEL;

    float v[4], s = 0.f, s2 = 0.f;
#pragma unroll
    for (int j = 0; j < 4; j++) {
        v[j] = x[tid + 256 * j];
        s  += v[j];
        s2 += v[j] * v[j];
    }
#pragma unroll
    for (int o = 16; o; o >>= 1) {
        s  += __shfl_down_sync(0xffffffffu, s,  o);
        s2 += __shfl_down_sync(0xffffffffu, s2, o);
    }
    __shared__ float ps[8], ps2[8];
    __shared__ float mu_s, rs_s;
    int w = tid >> 5, l = tid & 31;
    if (l == 0) { ps[w] = s; ps2[w] = s2; }
    __syncthreads();
    if (tid == 0) {
        float S = 0.f, S2 = 0.f;
#pragma unroll
        for (int i = 0; i < 8; i++) { S += ps[i]; S2 += ps2[i]; }
        float mu  = S * (1.0f / D_MODEL);
        float var = S2 * (1.0f / D_MODEL) - mu * mu;
        mu_s = mu;
        rs_s = rsqrtf(var + 1e-5f);
    }
    __syncthreads();
    float mu = mu_s, rs = rs_s;
#pragma unroll
    for (int j = 0; j < 4; j++) {
        int d = tid + 256 * j;
        float hn = (v[j] - mu) * rs * ln_g[d] + ln_b[d];
        g_hnorm[(size_t)t * D_MODEL + d] = hn;
        g_RI[(size_t)t * R_IN + d]       = hn;
        out[OFF_STAGE + (size_t)t * D_MODEL + d] = 0.0f;
    }
    if (t == 0 && tid < N_EXPERTS) g_cnt[tid] = 0;
}

// ================= 128x128x8 double-buffered SGEMM, 8x8 microtile =================
// MODE 0: plain C = act(A@B + bias)
// MODE 1: expert GEMM1 (gathered A rows via g_tok), C = gelu(...) into compacted list
// MODE 2: expert GEMM2, gate-weighted atomicAdd scatter into stage_out
// ACT: 1 = gelu (MODE 0/1 only)
template<int MODE, int ACT>
__global__ __launch_bounds__(256, 2) void gemm128(
    const float* __restrict__ A, int lda,
    const float* __restrict__ B, int ldb,
    const float* __restrict__ bias,
    float* __restrict__ C, int ldc, int K, int Mfull)
{
    __shared__ float As[2][8][128];
    __shared__ float Bs[2][8][128];
    __shared__ int   tok_s[128];
    __shared__ float wt_s[128];

    const int t  = threadIdx.x;
    const int m0 = blockIdx.x * 128;
    const int n0 = blockIdx.y * 128;
    const int e  = blockIdx.z;

    int M = Mfull;
    if (MODE != 0) {
        M = g_cnt[e];
        if (m0 >= M) return;
        B    += (size_t)e * K * ldb;
        bias += (size_t)e * ldc;
        if (MODE == 1) C += (size_t)e * NTOK * ldc;   // g_H1 block for this expert
        if (MODE == 2) A += (size_t)e * NTOK * lda;   // g_H1 block for this expert
        if (t < 128) {
            int idx = e * NTOK + min(m0 + t, M - 1);
            tok_s[t] = g_tok[idx];
            if (MODE == 2) wt_s[t] = g_wt[idx];
        }
        __syncthreads();
    }

    const int arow = t >> 1, akq = (t & 1) * 4;   // A ldg: row, k-quad
    const int bkr  = t >> 5, bnc = (t & 31) * 4;  // B ldg: k-row, n-col
    const int ty = t >> 4, tx = t & 15;

    const float* Aptr;
    if (MODE == 1)      Aptr = A + (size_t)tok_s[arow] * lda + akq;
    else if (MODE == 2) Aptr = A + (size_t)min(m0 + arow, M - 1) * lda + akq;
    else                Aptr = A + (size_t)(m0 + arow) * lda + akq;
    const float* Bptr = B + (size_t)bkr * ldb + n0 + bnc;

    // preload tile 0
    {
        float4 av = *reinterpret_cast<const float4*>(Aptr);
        float4 bv = *reinterpret_cast<const float4*>(Bptr);
        As[0][akq + 0][arow] = av.x;
        As[0][akq + 1][arow] = av.y;
        As[0][akq + 2][arow] = av.z;
        As[0][akq + 3][arow] = av.w;
        *reinterpret_cast<float4*>(&Bs[0][bkr][bnc]) = bv;
    }
    __syncthreads();

    float acc[8][8];
#pragma unroll
    for (int i = 0; i < 8; i++)
#pragma unroll
        for (int j = 0; j < 8; j++) acc[i][j] = 0.f;

    int buf = 0;
    for (int k0 = 8; k0 < K; k0 += 8) {
        float4 av2 = *reinterpret_cast<const float4*>(Aptr + k0);
        float4 bv2 = *reinterpret_cast<const float4*>(Bptr + (size_t)k0 * ldb);
#pragma unroll
        for (int kk = 0; kk < 8; kk++) {
            float a[8], b[8];
            *reinterpret_cast<float4*>(&a[0]) = *reinterpret_cast<const float4*>(&As[buf][kk][ty * 4]);
            *reinterpret_cast<float4*>(&a[4]) = *reinterpret_cast<const float4*>(&As[buf][kk][ty * 4 + 64]);
            *reinterpret_cast<float4*>(&b[0]) = *reinterpret_cast<const float4*>(&Bs[buf][kk][tx * 4]);
            *reinterpret_cast<float4*>(&b[4]) = *reinterpret_cast<const float4*>(&Bs[buf][kk][tx * 4 + 64]);
#pragma unroll
            for (int i = 0; i < 8; i++)
#pragma unroll
                for (int j = 0; j < 8; j++)
                    acc[i][j] = fmaf(a[i], b[j], acc[i][j]);
        }
        int nb = buf ^ 1;
        As[nb][akq + 0][arow] = av2.x;
        As[nb][akq + 1][arow] = av2.y;
        As[nb][akq + 2][arow] = av2.z;
        As[nb][akq + 3][arow] = av2.w;
        *reinterpret_cast<float4*>(&Bs[nb][bkr][bnc]) = bv2;
        __syncthreads();
        buf = nb;
    }
    // last tile
#pragma unroll
    for (int kk = 0; kk < 8; kk++) {
        float a[8], b[8];
        *reinterpret_cast<float4*>(&a[0]) = *reinterpret_cast<const float4*>(&As[buf][kk][ty * 4]);
        *reinterpret_cast<float4*>(&a[4]) = *reinterpret_cast<const float4*>(&As[buf][kk][ty * 4 + 64]);
        *reinterpret_cast<float4*>(&b[0]) = *reinterpret_cast<const float4*>(&Bs[buf][kk][tx * 4]);
        *reinterpret_cast<float4*>(&b[4]) = *reinterpret_cast<const float4*>(&Bs[buf][kk][tx * 4 + 64]);
#pragma unroll
        for (int i = 0; i < 8; i++)
#pragma unroll
            for (int j = 0; j < 8; j++)
                acc[i][j] = fmaf(a[i], b[j], acc[i][j]);
    }

    // epilogue
    float bb[8];
#pragma unroll
    for (int j = 0; j < 4; j++) {
        bb[j]     = bias[n0 + tx * 4 + j];
        bb[4 + j] = bias[n0 + 64 + tx * 4 + j];
    }

#pragma unroll
    for (int ih = 0; ih < 2; ih++) {
#pragma unroll
        for (int i = 0; i < 4; i++) {
            int rl = ih * 64 + ty * 4 + i;       // local row in tile
            int ri = ih * 4 + i;                 // acc row index
            int m  = m0 + rl;
            if (MODE == 0) {
                float4 v0, v1;
                float* p0 = &v0.x;
                float* p1 = &v1.x;
#pragma unroll
                for (int j = 0; j < 4; j++) {
                    float x0 = acc[ri][j]     + bb[j];
                    float x1 = acc[ri][4 + j] + bb[4 + j];
                    if (ACT) { x0 = gelu_tanh(x0); x1 = gelu_tanh(x1); }
                    p0[j] = x0; p1[j] = x1;
                }
                *reinterpret_cast<float4*>(&C[(size_t)m * ldc + n0 + tx * 4])      = v0;
                *reinterpret_cast<float4*>(&C[(size_t)m * ldc + n0 + 64 + tx * 4]) = v1;
            } else if (MODE == 1) {
                if (m < M) {
                    float4 v0, v1;
                    float* p0 = &v0.x;
                    float* p1 = &v1.x;
#pragma unroll
                    for (int j = 0; j < 4; j++) {
                        p0[j] = gelu_tanh(acc[ri][j]     + bb[j]);
                        p1[j] = gelu_tanh(acc[ri][4 + j] + bb[4 + j]);
                    }
                    *reinterpret_cast<float4*>(&C[(size_t)m * ldc + n0 + tx * 4])      = v0;
                    *reinterpret_cast<float4*>(&C[(size_t)m * ldc + n0 + 64 + tx * 4]) = v1;
                }
            } else {  // MODE == 2
                if (m < M) {
                    int   tok = tok_s[rl];
                    float wgt = wt_s[rl];
                    float* dst = C + (size_t)tok * ldc + n0;
#pragma unroll
                    for (int j = 0; j < 4; j++) {
                        atomicAdd(&dst[tx * 4 + j],      (acc[ri][j]     + bb[j])     * wgt);
                        atomicAdd(&dst[64 + tx * 4 + j], (acc[ri][4 + j] + bb[4 + j]) * wgt);
                    }
                }
            }
        }
    }
}

// ================= K5: router logits, top-2 softmax, small outputs, dispatch =================
__global__ __launch_bounds__(256) void k_router(
    const float* __restrict__ r_w2, const float* __restrict__ r_b2,
    const float* __restrict__ feat,
    const float* __restrict__ rr_w, const float* __restrict__ rr_b,
    float* __restrict__ out)
{
    int w = threadIdx.x >> 5, l = threadIdx.x & 31;
    int t = blockIdx.x * 8 + w;
    const float* rh = g_RHs + (size_t)t * R_HID;

    float acc[8] = {};
    for (int k = l; k < R_HID; k += 32) {
        float v = rh[k];
#pragma unroll
        for (int e = 0; e < 8; e++) acc[e] = fmaf(v, r_w2[k * 8 + e], acc[e]);
    }
#pragma unroll
    for (int o = 16; o; o >>= 1)
#pragma unroll
        for (int e = 0; e < 8; e++) acc[e] += __shfl_down_sync(0xffffffffu, acc[e], o);

    if (l == 0) {
        float lg[8];
#pragma unroll
        for (int e = 0; e < 8; e++) lg[e] = acc[e] + r_b2[e];
        int i1 = 0; float m1 = lg[0];
#pragma unroll
        for (int e = 1; e < 8; e++) if (lg[e] > m1) { m1 = lg[e]; i1 = e; }
        float m2 = -3.4e38f;
#pragma unroll
        for (int e = 0; e < 8; e++) if (e != i1 && lg[e] > m2) m2 = lg[e];
        float Z = 0.f, g[8];
#pragma unroll
        for (int e = 0; e < 8; e++) {
            if (lg[e] >= m2) { g[e] = expf(lg[e] - m1); Z += g[e]; }
            else g[e] = 0.f;
        }
        float invZ = 1.0f / Z;
#pragma unroll
        for (int e = 0; e < 8; e++) {
            g[e] *= invZ;
            out[OFF_GATE + (size_t)t * 8 + e] = g[e];
            out[OFF_SLOG + (size_t)t * 8 + e] = lg[e];
        }
#pragma unroll
        for (int gi = 0; gi < 4; gi++)
            out[OFF_GRP + (size_t)t * 4 + gi] = g[2 * gi] + g[2 * gi + 1];
        float fv[16];
#pragma unroll
        for (int i = 0; i < 16; i++) fv[i] = feat[(size_t)t * 16 + i];
#pragma unroll
        for (int e = 0; e < 8; e++) {
            float r = rr_b[e];
#pragma unroll
            for (int i = 0; i < 16; i++) r = fmaf(fv[i], rr_w[i * 8 + e], r);
            out[OFF_RULE + (size_t)t * 8 + e] = r;
        }
#pragma unroll
        for (int e = 0; e < 8; e++) {
            if (g[e] > 0.f) {
                int p = atomicAdd(&g_cnt[e], 1);
                g_tok[e * NTOK + p] = t;
                g_wt [e * NTOK + p] = g[e];
            }
        }
    }
}

// ================= K8: next_hidden = hidden + alpha * stage_out =================
__global__ __launch_bounds__(256) void k_finalize(
    const float* __restrict__ hidden,
    const float* __restrict__ alpha,
    float* __restrict__ out)
{
    size_t i = ((size_t)blockIdx.x * 256 + threadIdx.x) * 4;
    float a = alpha[0];
    float4 h = *reinterpret_cast<const float4*>(hidden + i);
    float4 s = *reinterpret_cast<const float4*>(out + OFF_STAGE + i);
    float4 r;
    r.x = h.x + a * s.x;
    r.y = h.y + a * s.y;
    r.z = h.z + a * s.z;
    r.w = h.w + a * s.w;
    *reinterpret_cast<float4*>(out + i) = r;
}

// ================= host launcher =================
extern "C" void kernel_launch(void* const* d_in, const int* in_sizes, int n_in,
                              void* d_out, int out_size)
{
    const float* hidden = (const float*)d_in[0];
    const float* feat   = (const float*)d_in[1];
    const float* bank   = (const float*)d_in[2];
    // d_in[3] = item_seq_len (unused by reference outputs)
    const float* ln_g   = (const float*)d_in[4];
    const float* ln_b   = (const float*)d_in[5];
    const float* fp_w1  = (const float*)d_in[6];
    const float* fp_b1  = (const float*)d_in[7];
    const float* fp_w2  = (const float*)d_in[8];
    const float* fp_b2  = (const float*)d_in[9];
    const float* r_w1   = (const float*)d_in[10];
    const float* r_b1   = (const float*)d_in[11];
    const float* r_w2   = (const float*)d_in[12];
    const float* r_b2   = (const float*)d_in[13];
    const float* rr_w   = (const float*)d_in[14];
    const float* rr_b   = (const float*)d_in[15];
    const float* e_w1   = (const float*)d_in[16];
    const float* e_b1   = (const float*)d_in[17];
    const float* e_w2   = (const float*)d_in[18];
    const float* e_b2   = (const float*)d_in[19];
    const float* alpha  = (const float*)d_in[20];
    float* out = (float*)d_out;

    float *p_RI, *p_P1, *p_RHs, *p_hn, *p_H1;
    cudaGetSymbolAddress((void**)&p_RI,  g_RI);
    cudaGetSymbolAddress((void**)&p_P1,  g_P1);
    cudaGetSymbolAddress((void**)&p_RHs, g_RHs);
    cudaGetSymbolAddress((void**)&p_hn,  g_hnorm);
    cudaGetSymbolAddress((void**)&p_H1,  g_H1);

    // K1: layernorm -> g_hnorm / g_RI[:, :1024], zero stage_out, reset counters
    k_layernorm<<<NTOK, 256>>>(hidden, ln_g, ln_b, out);

    // K2: P1 = gelu(bank @ fp_w1 + fp_b1)        [8192x512 @ 512x256]
    gemm128<0, 1><<<dim3(NTOK / 128, PROJ_DIM / 128), 256>>>(
        bank, RAW_FEAT, fp_w1, PROJ_DIM, fp_b1, p_P1, PROJ_DIM, RAW_FEAT, NTOK);

    // K3: proj = P1 @ fp_w2 + fp_b2  -> g_RI[:, 1024:1280]
    gemm128<0, 0><<<dim3(NTOK / 128, PROJ_DIM / 128), 256>>>(
        p_P1, PROJ_DIM, fp_w2, PROJ_DIM, fp_b2, p_RI + D_MODEL, R_IN, PROJ_DIM, NTOK);

    // K4: RH = gelu(RI @ r_w1 + r_b1)            [8192x1280 @ 1280x256]
    gemm128<0, 1><<<dim3(NTOK / 128, R_HID / 128), 256>>>(
        p_RI, R_IN, r_w1, R_HID, r_b1, p_RHs, R_HID, R_IN, NTOK);

    // K5: logits, top-2 softmax, small outputs, expert dispatch
    k_router<<<NTOK / 8, 256>>>(r_w2, r_b2, feat, rr_w, rr_b, out);

    // K6: per-expert gathered GEMM1 (gelu) -> g_H1
    gemm128<1, 1><<<dim3(NTOK / 128, E_HID / 128, N_EXPERTS), 256>>>(
        p_hn, D_MODEL, e_w1, E_HID, e_b1, p_H1, E_HID, D_MODEL, 0);

    // K7: per-expert GEMM2, gate-weighted atomic accumulate into stage_out
    gemm128<2, 0><<<dim3(NTOK / 128, D_MODEL / 128, N_EXPERTS), 256>>>(
        p_H1, E_HID, e_w2, D_MODEL, e_b2, out + OFF_STAGE, D_MODEL, E_HID, 0);

    // K8: next_hidden = hidden + alpha * stage_out
    k_finalize<<<(NTOK * D_MODEL) / (256 * 4), 256>>>(hidden, alpha, out);
}